// round 1
// baseline (speedup 1.0000x reference)
#include <cuda_runtime.h>
#include <cuda_bf16.h>
#include <math.h>

// Problem constants (fixed shapes from reference)
#define PB   8      // batch
#define PF   16     // frames
#define PNS  196    // spatial tokens per frame
#define PJ   24     // joints
#define PH   8      // heads
#define PDH  64     // head dim
#define PDIM 512
#define PROT 32
#define PN   (PJ + PF * PNS)   // 3160
#define PBH  (PB * PH)         // 64
#define PM1  (PB * PN)         // 25280  (divisible by 64: 395*64)
#define NKEY (PJ + PNS)        // 220 keys in spatial attention

// Scratch (device globals -- allocation-free per harness rules)
__device__ float g_q[(size_t)PBH * PN * PDH];   // head-major, pre-scaled
__device__ float g_k[(size_t)PBH * PN * PDH];
__device__ float g_v[(size_t)PBH * PN * PDH];
__device__ float g_o[(size_t)PB * PN * (PH * PDH)];  // (b, n, h*d) row-major

// ---------------------------------------------------------------------------
// GEMM 1: qkv = x @ w_qkv ; epilogue scatters to head-major q/k/v, scales q.
// Tile: BM=64, BN=128, BK=16, 256 threads, each thread 4x8.
// M=25280 (395 tiles), N=1536 (12 tiles), K=512 -- all exact, no bounds checks.
// ---------------------------------------------------------------------------
__global__ __launch_bounds__(256) void gemm_qkv_kernel(
    const float* __restrict__ A, const float* __restrict__ Bw)
{
    __shared__ float As[16][64];
    __shared__ float Bs[16][128];
    const int tid = threadIdx.x;
    const int tx = tid & 15;     // col group (8 cols each)
    const int ty = tid >> 4;     // row group (4 rows each)
    const int row0 = blockIdx.y * 64;
    const int col0 = blockIdx.x * 128;

    float acc[4][8];
    #pragma unroll
    for (int i = 0; i < 4; i++)
        #pragma unroll
        for (int j = 0; j < 8; j++) acc[i][j] = 0.f;

    const int arow = tid >> 2;          // 0..63
    const int ak   = (tid & 3) * 4;     // 0,4,8,12

    for (int kt = 0; kt < PDIM; kt += 16) {
        float4 av = *(const float4*)(A + (size_t)(row0 + arow) * PDIM + kt + ak);
        As[ak + 0][arow] = av.x;
        As[ak + 1][arow] = av.y;
        As[ak + 2][arow] = av.z;
        As[ak + 3][arow] = av.w;
        #pragma unroll
        for (int i = 0; i < 2; i++) {
            int f4 = tid + i * 256;
            int bk = f4 >> 5;
            int bc = (f4 & 31) * 4;
            *(float4*)(&Bs[bk][bc]) =
                *(const float4*)(Bw + (size_t)(kt + bk) * (3 * PDIM) + col0 + bc);
        }
        __syncthreads();
        #pragma unroll
        for (int k = 0; k < 16; k++) {
            float ra[4], rb[8];
            #pragma unroll
            for (int i = 0; i < 4; i++) ra[i] = As[k][ty * 4 + i];
            #pragma unroll
            for (int j = 0; j < 8; j++) rb[j] = Bs[k][tx * 8 + j];
            #pragma unroll
            for (int i = 0; i < 4; i++)
                #pragma unroll
                for (int j = 0; j < 8; j++) acc[i][j] += ra[i] * rb[j];
        }
        __syncthreads();
    }

    // Epilogue: scatter into head-major layouts
    #pragma unroll
    for (int i = 0; i < 4; i++) {
        int row = row0 + ty * 4 + i;
        int b = row / PN;
        int n = row - b * PN;
        #pragma unroll
        for (int j = 0; j < 8; j++) {
            int col = col0 + tx * 8 + j;
            int which = col >> 9;         // 0=q,1=k,2=v
            int c = col & 511;
            int h = c >> 6;
            int d = c & 63;
            size_t dst = ((size_t)(b * PH + h) * PN + n) * PDH + d;
            float val = acc[i][j];
            if (which == 0)      g_q[dst] = val * 0.125f;   // 64^-0.5
            else if (which == 1) g_k[dst] = val;
            else                 g_v[dst] = val;
        }
    }
}

// ---------------------------------------------------------------------------
// Joints attention: per (bh, j): softmax(q_j . K[0..3159]) @ V
// ---------------------------------------------------------------------------
__global__ __launch_bounds__(256) void joints_attn_kernel()
{
    __shared__ float qs[PDH];
    __shared__ float logits[PN];
    __shared__ float redbuf[8];
    __shared__ float scal;
    __shared__ float oacc[4 * PDH];

    const int bh = blockIdx.y;
    const int j  = blockIdx.x;
    const int tid = threadIdx.x;
    const float* kb = g_k + (size_t)bh * PN * PDH;
    const float* vb = g_v + (size_t)bh * PN * PDH;

    if (tid < PDH) qs[tid] = g_q[((size_t)bh * PN + j) * PDH + tid];
    __syncthreads();

    float lmax = -1e30f;
    for (int n = tid; n < PN; n += 256) {
        const float4* k4 = (const float4*)(kb + (size_t)n * PDH);
        float dot = 0.f;
        #pragma unroll
        for (int d4 = 0; d4 < 16; d4++) {
            float4 kv = k4[d4];
            dot += qs[4 * d4 + 0] * kv.x + qs[4 * d4 + 1] * kv.y +
                   qs[4 * d4 + 2] * kv.z + qs[4 * d4 + 3] * kv.w;
        }
        logits[n] = dot;
        lmax = fmaxf(lmax, dot);
    }
    // block reduce max
    #pragma unroll
    for (int o = 16; o > 0; o >>= 1) lmax = fmaxf(lmax, __shfl_xor_sync(0xffffffffu, lmax, o));
    if ((tid & 31) == 0) redbuf[tid >> 5] = lmax;
    __syncthreads();
    if (tid == 0) {
        float m = redbuf[0];
        #pragma unroll
        for (int w = 1; w < 8; w++) m = fmaxf(m, redbuf[w]);
        scal = m;
    }
    __syncthreads();
    const float gmax = scal;
    __syncthreads();

    float lsum = 0.f;
    for (int n = tid; n < PN; n += 256) {
        float e = __expf(logits[n] - gmax);
        logits[n] = e;
        lsum += e;
    }
    #pragma unroll
    for (int o = 16; o > 0; o >>= 1) lsum += __shfl_xor_sync(0xffffffffu, lsum, o);
    if ((tid & 31) == 0) redbuf[tid >> 5] = lsum;
    __syncthreads();
    if (tid == 0) {
        float s = 0.f;
        #pragma unroll
        for (int w = 0; w < 8; w++) s += redbuf[w];
        scal = s;
    }
    __syncthreads();
    const float gsum = scal;

    // weighted sum over V: 4 n-groups x 64 dims
    const int d = tid & 63;
    const int g = tid >> 6;
    float acc = 0.f;
    for (int n = g; n < PN; n += 4)
        acc += logits[n] * vb[(size_t)n * PDH + d];
    __syncthreads();           // done reading logits region semantics (oacc separate)
    oacc[g * PDH + d] = acc;
    __syncthreads();
    if (tid < PDH) {
        float s = oacc[tid] + oacc[PDH + tid] + oacc[2 * PDH + tid] + oacc[3 * PDH + tid];
        int b = bh >> 3, h = bh & 7;
        g_o[((size_t)(b * PN + j)) * (PH * PDH) + h * PDH + tid] = s / gsum;
    }
}

// ---------------------------------------------------------------------------
// Spatial attention: per (bh, f): 196 queries x 220 keys (24 joint + 196 RoPE'd)
// Dynamic smem: K tile + V tile = 2 * 220 * 64 floats = 112640 B
// ---------------------------------------------------------------------------
#define SPATIAL_SMEM (2 * NKEY * PDH * (int)sizeof(float))

__global__ __launch_bounds__(256) void spatial_attn_kernel(
    const float* __restrict__ sinp, const float* __restrict__ cosp)
{
    extern __shared__ float sm[];
    float* ks = sm;
    float* vs = sm + NKEY * PDH;

    const int bh = blockIdx.y;
    const int f  = blockIdx.x;
    const int tid = threadIdx.x;
    const size_t base = (size_t)bh * PN * PDH;

    // Load K (RoPE the frame keys) and V
    for (int idx = tid; idx < NKEY * PDH; idx += 256) {
        int nrow = idx >> 6;
        int d = idx & 63;
        int gn = (nrow < PJ) ? nrow : (PJ + f * PNS + (nrow - PJ));
        float kv = g_k[base + (size_t)gn * PDH + d];
        float vv = g_v[base + (size_t)gn * PDH + d];
        if (nrow >= PJ && d < PROT) {
            int s = nrow - PJ;
            float c = cosp[s * PROT + d];
            float sn = sinp[s * PROT + d];
            float partner = g_k[base + (size_t)gn * PDH + (d ^ 1)];
            kv = (d & 1) ? (kv * c + partner * sn) : (kv * c - partner * sn);
        }
        ks[idx] = kv;
        vs[idx] = vv;
    }
    __syncthreads();

    if (tid < PNS) {
        const int s = tid;
        const int gn = PJ + f * PNS + s;
        float qr[PDH];
        const float* qp = g_q + base + (size_t)gn * PDH;
        #pragma unroll
        for (int d = 0; d < PDH; d++) qr[d] = qp[d];
        // RoPE on q (first 32 dims)
        #pragma unroll
        for (int d = 0; d < PROT; d += 2) {
            float c0 = cosp[s * PROT + d],     s0 = sinp[s * PROT + d];
            float c1 = cosp[s * PROT + d + 1], s1 = sinp[s * PROT + d + 1];
            float a = qr[d], b2 = qr[d + 1];
            qr[d]     = a * c0 - b2 * s0;
            qr[d + 1] = b2 * c1 + a * s1;
        }
        // pass 1: online max + sum
        float m = -1e30f, l = 0.f;
        for (int n = 0; n < NKEY; n++) {
            float dot = 0.f;
            #pragma unroll
            for (int d = 0; d < PDH; d++) dot += qr[d] * ks[n * PDH + d];
            float nm = fmaxf(m, dot);
            l = l * __expf(m - nm) + __expf(dot - nm);
            m = nm;
        }
        // pass 2: recompute + weighted V accumulation
        float out[PDH];
        #pragma unroll
        for (int d = 0; d < PDH; d++) out[d] = 0.f;
        for (int n = 0; n < NKEY; n++) {
            float dot = 0.f;
            #pragma unroll
            for (int d = 0; d < PDH; d++) dot += qr[d] * ks[n * PDH + d];
            float p = __expf(dot - m);
            #pragma unroll
            for (int d = 0; d < PDH; d++) out[d] += p * vs[n * PDH + d];
        }
        const float inv = 1.f / l;
        const int b = bh >> 3, h = bh & 7;
        float* op = g_o + ((size_t)(b * PN + gn)) * (PH * PDH) + h * PDH;
        #pragma unroll
        for (int d = 0; d < PDH; d++) op[d] = out[d] * inv;
    }
}

// ---------------------------------------------------------------------------
// GEMM 2: out = g_o @ w_out + b_out. M=25280, N=512, K=512.
// Same tiling: BM=64, BN=128, BK=16.
// ---------------------------------------------------------------------------
__global__ __launch_bounds__(256) void gemm_out_kernel(
    const float* __restrict__ Bw, const float* __restrict__ bias,
    float* __restrict__ out)
{
    __shared__ float As[16][64];
    __shared__ float Bs[16][128];
    const int tid = threadIdx.x;
    const int tx = tid & 15;
    const int ty = tid >> 4;
    const int row0 = blockIdx.y * 64;
    const int col0 = blockIdx.x * 128;
    const float* A = g_o;

    float acc[4][8];
    #pragma unroll
    for (int i = 0; i < 4; i++)
        #pragma unroll
        for (int j = 0; j < 8; j++) acc[i][j] = 0.f;

    const int arow = tid >> 2;
    const int ak   = (tid & 3) * 4;

    for (int kt = 0; kt < PDIM; kt += 16) {
        float4 av = *(const float4*)(A + (size_t)(row0 + arow) * PDIM + kt + ak);
        As[ak + 0][arow] = av.x;
        As[ak + 1][arow] = av.y;
        As[ak + 2][arow] = av.z;
        As[ak + 3][arow] = av.w;
        #pragma unroll
        for (int i = 0; i < 2; i++) {
            int f4 = tid + i * 256;
            int bk = f4 >> 5;
            int bc = (f4 & 31) * 4;
            *(float4*)(&Bs[bk][bc]) =
                *(const float4*)(Bw + (size_t)(kt + bk) * PDIM + col0 + bc);
        }
        __syncthreads();
        #pragma unroll
        for (int k = 0; k < 16; k++) {
            float ra[4], rb[8];
            #pragma unroll
            for (int i = 0; i < 4; i++) ra[i] = As[k][ty * 4 + i];
            #pragma unroll
            for (int j = 0; j < 8; j++) rb[j] = Bs[k][tx * 8 + j];
            #pragma unroll
            for (int i = 0; i < 4; i++)
                #pragma unroll
                for (int j = 0; j < 8; j++) acc[i][j] += ra[i] * rb[j];
        }
        __syncthreads();
    }

    #pragma unroll
    for (int i = 0; i < 4; i++) {
        int row = row0 + ty * 4 + i;
        #pragma unroll
        for (int j = 0; j < 8; j++) {
            int col = col0 + tx * 8 + j;
            out[(size_t)row * PDIM + col] = acc[i][j] + bias[col];
        }
    }
}

// ---------------------------------------------------------------------------
extern "C" void kernel_launch(void* const* d_in, const int* in_sizes, int n_in,
                              void* d_out, int out_size)
{
    (void)in_sizes; (void)n_in; (void)out_size;
    const float* x      = (const float*)d_in[0];
    const float* w_qkv  = (const float*)d_in[1];
    const float* w_out  = (const float*)d_in[2];
    const float* b_out  = (const float*)d_in[3];
    const float* sinp   = (const float*)d_in[4];
    const float* cosp   = (const float*)d_in[5];
    float* out = (float*)d_out;

    cudaFuncSetAttribute(spatial_attn_kernel,
                         cudaFuncAttributeMaxDynamicSharedMemorySize, SPATIAL_SMEM);

    // 1) QKV projection (scatter to head-major scratch)
    gemm_qkv_kernel<<<dim3(3 * PDIM / 128, PM1 / 64), 256>>>(x, w_qkv);
    // 2) Joints attention (24 queries, full 3160-key context, no RoPE)
    joints_attn_kernel<<<dim3(PJ, PBH), 256>>>();
    // 3) Spatial attention (per frame, RoPE'd, 24 joint keys prepended)
    spatial_attn_kernel<<<dim3(PF, PBH), 256, SPATIAL_SMEM>>>(sinp, cosp);
    // 4) Output projection + bias
    gemm_out_kernel<<<dim3(PDIM / 128, PM1 / 64), 256>>>(w_out, b_out, out);
}

// round 10
// speedup vs baseline: 2.3360x; 2.3360x over previous
#include <cuda_runtime.h>
#include <cuda_bf16.h>
#include <math.h>
#include <stdint.h>

// Problem constants
#define PB   8
#define PF   16
#define PNS  196
#define PJ   24
#define PH   8
#define PDH  64
#define PDIM 512
#define PROT 32
#define PN   (PJ + PF * PNS)   // 3160
#define PBH  (PB * PH)         // 64
#define PM1  (PB * PN)         // 25280
#define NKEY (PJ + PNS)        // 220
#define NQKV (3 * PDIM)        // 1536

// -------------------- scratch (device globals) ------------------------------
__device__ __align__(16) float g_q[(size_t)PBH * PN * PDH];
__device__ __align__(16) float g_k[(size_t)PBH * PN * PDH];
__device__ __align__(16) float g_v[(size_t)PBH * PN * PDH];
__device__ __align__(16) float g_o[(size_t)PB * PN * (PH * PDH)];

// bf16 hi/lo split operands (A padded by 128 rows for ragged last M tile; pad
// rows are never written => stay zero from module init)
__device__ __align__(16) __nv_bfloat16 g_xhi[(size_t)(PM1 + 128) * PDIM];
__device__ __align__(16) __nv_bfloat16 g_xlo[(size_t)(PM1 + 128) * PDIM];
__device__ __align__(16) __nv_bfloat16 g_ohi[(size_t)(PM1 + 128) * PDIM];
__device__ __align__(16) __nv_bfloat16 g_olo[(size_t)(PM1 + 128) * PDIM];
__device__ __align__(16) __nv_bfloat16 g_wqkvT_hi[(size_t)NQKV * PDIM];  // [N][K]
__device__ __align__(16) __nv_bfloat16 g_wqkvT_lo[(size_t)NQKV * PDIM];
__device__ __align__(16) __nv_bfloat16 g_woutT_hi[(size_t)PDIM * PDIM];  // [N][K]
__device__ __align__(16) __nv_bfloat16 g_woutT_lo[(size_t)PDIM * PDIM];

// joints attention scratch
__device__ __align__(16) float g_jp[(size_t)PBH * PJ * PN];   // exp(logits)
__device__ __align__(16) float g_jout[4 * PBH * PJ * PDH];    // partial PV
__device__ __align__(16) float g_jpsum[4 * PBH * PJ];         // partial sums

#define JCHUNK 792   // per-bx key range (multiple of 8; last block gets 784)

// -------------------- asm helpers -------------------------------------------
__device__ __forceinline__ uint32_t smem_to_u32(const void* p) {
    uint32_t a;
    asm("{ .reg .u64 t; cvta.to.shared.u64 t, %1; cvt.u32.u64 %0, t; }" : "=r"(a) : "l"(p));
    return a;
}
__device__ __forceinline__ void ldsm4(uint32_t* r, uint32_t addr) {
    asm volatile("ldmatrix.sync.aligned.m8n8.x4.shared.b16 {%0,%1,%2,%3}, [%4];"
        : "=r"(r[0]), "=r"(r[1]), "=r"(r[2]), "=r"(r[3]) : "r"(addr));
}
__device__ __forceinline__ void mma16816(float* c, const uint32_t* a, const uint32_t* b) {
    asm volatile("mma.sync.aligned.m16n8k16.row.col.f32.bf16.bf16.f32 "
        "{%0,%1,%2,%3}, {%4,%5,%6,%7}, {%8,%9}, {%0,%1,%2,%3};"
        : "+f"(c[0]), "+f"(c[1]), "+f"(c[2]), "+f"(c[3])
        : "r"(a[0]), "r"(a[1]), "r"(a[2]), "r"(a[3]), "r"(b[0]), "r"(b[1]));
}

// -------------------- conversion kernels ------------------------------------
__global__ void convert_split_kernel(const float* __restrict__ src,
                                     __nv_bfloat16* __restrict__ hi,
                                     __nv_bfloat16* __restrict__ lo, int n4) {
    int i = blockIdx.x * blockDim.x + threadIdx.x;
    if (i >= n4) return;
    float4 v = ((const float4*)src)[i];
    __nv_bfloat16 h0 = __float2bfloat16(v.x), h1 = __float2bfloat16(v.y);
    __nv_bfloat16 h2 = __float2bfloat16(v.z), h3 = __float2bfloat16(v.w);
    hi[4 * i + 0] = h0; hi[4 * i + 1] = h1; hi[4 * i + 2] = h2; hi[4 * i + 3] = h3;
    lo[4 * i + 0] = __float2bfloat16(v.x - __bfloat162float(h0));
    lo[4 * i + 1] = __float2bfloat16(v.y - __bfloat162float(h1));
    lo[4 * i + 2] = __float2bfloat16(v.z - __bfloat162float(h2));
    lo[4 * i + 3] = __float2bfloat16(v.w - __bfloat162float(h3));
}

// wT[n*K + k] = w[k*N + n], split into hi/lo
__global__ void convert_wT_kernel(const float* __restrict__ w,
                                  __nv_bfloat16* __restrict__ hi,
                                  __nv_bfloat16* __restrict__ lo, int K, int Nn) {
    int i = blockIdx.x * blockDim.x + threadIdx.x;
    if (i >= K * Nn) return;
    int n = i / K, k = i - n * K;
    float v = w[(size_t)k * Nn + n];
    __nv_bfloat16 h = __float2bfloat16(v);
    hi[i] = h;
    lo[i] = __float2bfloat16(v - __bfloat162float(h));
}

// -------------------- mma.sync split-bf16 GEMM -------------------------------
// C[128x128] = A[128x512] @ B^T, B stored [N][K] K-major. 3-term hi/lo split.
// 8 warps: warp (wm, wn) owns 64x32; m16n8k16 HMMA; K-step 64; smem pitch 144B.
#define TILE_B   (128 * 144)        // 18432 bytes per operand tile
#define GEMM_SMEM (4 * TILE_B)      // 73728 (epilogue reuses 128*132*4=67584)

template <int MODE>
__global__ __launch_bounds__(256, 1) void mma_gemm_kernel(
    const __nv_bfloat16* __restrict__ Ahi, const __nv_bfloat16* __restrict__ Alo,
    const __nv_bfloat16* __restrict__ Bhi, const __nv_bfloat16* __restrict__ Blo,
    const float* __restrict__ bias, float* __restrict__ outp)
{
    extern __shared__ char sm[];
    const uint32_t smb = smem_to_u32(sm);
    const int tid = threadIdx.x;
    const int lane = tid & 31;
    const int wid = tid >> 5;
    const int wm = wid & 1;        // 0..1 -> m offset 64*wm
    const int wn = wid >> 1;       // 0..3 -> n offset 32*wn
    const int row0 = blockIdx.y * 128;
    const int col0 = blockIdx.x * 128;

    float c[4][4][4];
    #pragma unroll
    for (int i = 0; i < 4; i++)
        #pragma unroll
        for (int j = 0; j < 4; j++)
            #pragma unroll
            for (int e = 0; e < 4; e++) c[i][j][e] = 0.f;

    const int frow = tid >> 3;     // 0..31
    const int fcol = tid & 7;      // 16B chunk within 128B row

    // ldmatrix per-lane byte offsets (within a tile)
    const uint32_t offA = (uint32_t)(wm * 64 + (lane & 15)) * 144 + ((lane >> 4) << 3) * 2;
    const uint32_t offB = (uint32_t)(wn * 32 + ((lane >> 4) << 3) + (lane & 7)) * 144 +
                          (((lane >> 3) & 1) << 3) * 2;

    for (int kb = 0; kb < 8; kb++) {
        #pragma unroll
        for (int i = 0; i < 4; i++) {
            int row = frow + 32 * i;
            size_t gA = (size_t)(row0 + row) * PDIM + kb * 64 + fcol * 8;
            size_t gB = (size_t)(col0 + row) * PDIM + kb * 64 + fcol * 8;
            uint32_t so = (uint32_t)row * 144 + fcol * 16;
            *(uint4*)(sm + 0 * TILE_B + so) = *(const uint4*)(Ahi + gA);
            *(uint4*)(sm + 1 * TILE_B + so) = *(const uint4*)(Alo + gA);
            *(uint4*)(sm + 2 * TILE_B + so) = *(const uint4*)(Bhi + gB);
            *(uint4*)(sm + 3 * TILE_B + so) = *(const uint4*)(Blo + gB);
        }
        __syncthreads();

        #pragma unroll
        for (int ks = 0; ks < 4; ks++) {
            uint32_t ah[4][4], al[4][4], bhv[2][4], blv[2][4];
            #pragma unroll
            for (int mf = 0; mf < 4; mf++) {
                ldsm4(ah[mf], smb + 0 * TILE_B + offA + mf * (16 * 144) + ks * 32);
                ldsm4(al[mf], smb + 1 * TILE_B + offA + mf * (16 * 144) + ks * 32);
            }
            #pragma unroll
            for (int nb = 0; nb < 2; nb++) {
                ldsm4(bhv[nb], smb + 2 * TILE_B + offB + nb * (16 * 144) + ks * 32);
                ldsm4(blv[nb], smb + 3 * TILE_B + offB + nb * (16 * 144) + ks * 32);
            }
            #pragma unroll
            for (int mf = 0; mf < 4; mf++) {
                #pragma unroll
                for (int nf = 0; nf < 4; nf++) {
                    const uint32_t* ph = &bhv[nf >> 1][(nf & 1) * 2];
                    const uint32_t* pl = &blv[nf >> 1][(nf & 1) * 2];
                    mma16816(c[mf][nf], ah[mf], ph);
                    mma16816(c[mf][nf], ah[mf], pl);
                    mma16816(c[mf][nf], al[mf], ph);
                }
            }
        }
        __syncthreads();
    }

    // stage C into smem (pitch 132 floats), then coalesced global writes
    float* ts = (float*)sm;
    const int g = lane >> 2, tg = lane & 3;
    #pragma unroll
    for (int mf = 0; mf < 4; mf++) {
        #pragma unroll
        for (int nf = 0; nf < 4; nf++) {
            int r = wm * 64 + mf * 16 + g;
            int cc = wn * 32 + nf * 8 + 2 * tg;
            ts[r * 132 + cc]           = c[mf][nf][0];
            ts[r * 132 + cc + 1]       = c[mf][nf][1];
            ts[(r + 8) * 132 + cc]     = c[mf][nf][2];
            ts[(r + 8) * 132 + cc + 1] = c[mf][nf][3];
        }
    }
    __syncthreads();

    if (MODE == 0) {
        int which = col0 >> 9;
        int c0 = col0 & 511;
        int h0 = c0 >> 6;
        float* dst = which == 0 ? g_q : (which == 1 ? g_k : g_v);
        float scale = which == 0 ? 0.125f : 1.0f;
        #pragma unroll
        for (int t = 0; t < 16; t++) {
            int idx = tid + t * 256;
            int row = idx >> 5;
            int cc = (idx & 31) * 4;
            int m = row0 + row;
            if (m >= PM1) continue;
            int b = m / PN, n = m - b * PN;
            int h = h0 + (cc >> 6), d = cc & 63;
            float4 v = *(float4*)&ts[row * 132 + cc];
            v.x *= scale; v.y *= scale; v.z *= scale; v.w *= scale;
            *(float4*)&dst[(((size_t)(b * PH + h) * PN + n) << 6) + d] = v;
        }
    } else {
        #pragma unroll
        for (int t = 0; t < 16; t++) {
            int idx = tid + t * 256;
            int row = idx >> 5;
            int cc = (idx & 31) * 4;
            int m = row0 + row;
            if (m >= PM1) continue;
            int col = col0 + cc;
            float4 v = *(float4*)&ts[row * 132 + cc];
            float4 bv = *(const float4*)&bias[col];
            v.x += bv.x; v.y += bv.y; v.z += bv.z; v.w += bv.w;
            *(float4*)&outp[(size_t)m * PDIM + col] = v;
        }
    }
}

// -------------------- joints attention ---------------------------------------
// J1: exp-logits. Block = 64 threads, 256 keys, 24 joints; thread = 4 keys.
#define J1_SMEM (PJ * PDH * 4 + PDH * 257 * 4)   // 6144 + 65792 = 71936

__global__ __launch_bounds__(64) void joints_logits_kernel()
{
    extern __shared__ float smf[];
    float* qs  = smf;                 // [24][64]
    float* ksT = smf + PJ * PDH;      // [64][257]

    const int bh = blockIdx.y;
    const int kb = blockIdx.x;        // 0..12
    const int tid = threadIdx.x;      // 0..63
    const int n0 = kb * 256;
    const size_t base = (size_t)bh * PN * PDH;

    #pragma unroll
    for (int i = 0; i < 24; i++)
        qs[tid + 64 * i] = g_q[base + tid + 64 * i];   // rows 0..23 contiguous

    #pragma unroll 8
    for (int i = 0; i < 64; i++) {
        int idx = tid + 64 * i;       // 0..4095
        int key = idx >> 4;
        int d4 = (idx & 15) << 2;
        int n = n0 + key;
        if (n < PN) {
            float4 v = *(const float4*)&g_k[base + (size_t)n * PDH + d4];
            ksT[(d4 + 0) * 257 + key] = v.x;
            ksT[(d4 + 1) * 257 + key] = v.y;
            ksT[(d4 + 2) * 257 + key] = v.z;
            ksT[(d4 + 3) * 257 + key] = v.w;
        }
    }
    __syncthreads();

    float acc[24][4];
    #pragma unroll
    for (int j = 0; j < 24; j++)
        #pragma unroll
        for (int s = 0; s < 4; s++) acc[j][s] = 0.f;

    for (int d = 0; d < PDH; d++) {
        float k0 = ksT[d * 257 + tid];
        float k1 = ksT[d * 257 + tid + 64];
        float k2 = ksT[d * 257 + tid + 128];
        float k3 = ksT[d * 257 + tid + 192];
        #pragma unroll
        for (int j = 0; j < 24; j++) {
            float qv = qs[j * 64 + d];
            acc[j][0] += qv * k0;
            acc[j][1] += qv * k1;
            acc[j][2] += qv * k2;
            acc[j][3] += qv * k3;
        }
    }

    #pragma unroll
    for (int s = 0; s < 4; s++) {
        int n = n0 + tid + 64 * s;
        if (n < PN) {
            #pragma unroll
            for (int j = 0; j < 24; j++)
                g_jp[((size_t)bh * PJ + j) * PN + n] = __expf(acc[j][s]);
        }
    }
}

// J2: partial PV + partial sums. Block = 256 threads, n-range JCHUNK per block
// (multiple of 8 => float4 loads of g_jp stay 16B-aligned).
// thread i: d = i%64, j in {i/64 + 4t, t<6}
#define J2_SMEM (256 * PDH * 4 + PJ * 256 * 4)    // 65536 + 24576 = 90112

__global__ __launch_bounds__(256) void joints_pv_kernel()
{
    extern __shared__ float smf[];
    float* vs = smf;                  // [256][64]
    float* ps = smf + 256 * PDH;      // [24][256]

    const int bh = blockIdx.y;
    const int bx = blockIdx.x;        // 0..3
    const int tid = threadIdx.x;
    const int d = tid & 63;
    const int jg = tid >> 6;          // 0..3
    const int n0 = bx * JCHUNK;
    int total = PN - n0; if (total > JCHUNK) total = JCHUNK;   // 792/792/792/784
    const size_t base = (size_t)bh * PN * PDH;

    float out[6], psum[6];
    #pragma unroll
    for (int t = 0; t < 6; t++) { out[t] = 0.f; psum[t] = 0.f; }

    for (int c = 0; c < 4; c++) {
        int n0c = n0 + c * 256;
        int cnt = total - c * 256;
        if (cnt <= 0) break;
        if (cnt > 256) cnt = 256;

        // load V chunk (zero-pad tail)
        #pragma unroll
        for (int t = 0; t < 16; t++) {
            int idx = tid + t * 256;          // 0..4095
            int key = idx >> 4;
            int d4 = (idx & 15) << 2;
            float4 v = make_float4(0.f, 0.f, 0.f, 0.f);
            if (key < cnt) v = *(const float4*)&g_v[base + (size_t)(n0c + key) * PDH + d4];
            *(float4*)&vs[key * PDH + d4] = v;
        }
        // load p chunk (zero-pad tail); n0c is multiple of 8 -> aligned
        #pragma unroll
        for (int t = 0; t < 6; t++) {
            int idx = tid + t * 256;          // 0..1535
            int j = idx >> 6;
            int nn4 = (idx & 63) << 2;
            float4 v;
            if (nn4 + 3 < cnt) {
                v = *(const float4*)&g_jp[((size_t)bh * PJ + j) * PN + n0c + nn4];
            } else {
                float tmp[4];
                #pragma unroll
                for (int e = 0; e < 4; e++)
                    tmp[e] = (nn4 + e < cnt)
                        ? g_jp[((size_t)bh * PJ + j) * PN + n0c + nn4 + e] : 0.f;
                v = make_float4(tmp[0], tmp[1], tmp[2], tmp[3]);
            }
            *(float4*)&ps[j * 256 + nn4] = v;
        }
        __syncthreads();

        for (int nn = 0; nn < 256; nn += 4) {
            float v0 = vs[(nn + 0) * PDH + d];
            float v1 = vs[(nn + 1) * PDH + d];
            float v2 = vs[(nn + 2) * PDH + d];
            float v3 = vs[(nn + 3) * PDH + d];
            #pragma unroll
            for (int t = 0; t < 6; t++) {
                int j = jg + 4 * t;
                float4 p4 = *(float4*)&ps[j * 256 + nn];
                out[t] += p4.x * v0 + p4.y * v1 + p4.z * v2 + p4.w * v3;
                psum[t] += p4.x + p4.y + p4.z + p4.w;
            }
        }
        __syncthreads();
    }

    #pragma unroll
    for (int t = 0; t < 6; t++) {
        int j = jg + 4 * t;
        g_jout[(((size_t)bx * PBH + bh) * PJ + j) * PDH + d] = out[t];
        if (d == 0) g_jpsum[((size_t)bx * PBH + bh) * PJ + j] = psum[t];
    }
}

// J3: combine partials, divide, write g_o
__global__ __launch_bounds__(256) void joints_finish_kernel()
{
    const int bh = blockIdx.x;
    const int tid = threadIdx.x;
    const int d = tid & 63;
    const int jg = tid >> 6;
    const int b = bh >> 3, h = bh & 7;
    #pragma unroll
    for (int t = 0; t < 6; t++) {
        int j = jg + 4 * t;
        float o = 0.f, s = 0.f;
        #pragma unroll
        for (int bx = 0; bx < 4; bx++) {
            o += g_jout[(((size_t)bx * PBH + bh) * PJ + j) * PDH + d];
            s += g_jpsum[((size_t)bx * PBH + bh) * PJ + j];
        }
        g_o[((size_t)(b * PN + j)) * (PH * PDH) + h * PDH + d] = o / s;
    }
}

// -------------------- spatial attention (single-dot-pass flash) ---------------
// smem: ks[220*64] + vs[220*64] + dots[196][113] = 201232 bytes
#define DPITCH 113
#define SPATIAL_SMEM ((2 * NKEY * PDH + PNS * DPITCH) * (int)sizeof(float))

__global__ __launch_bounds__(256) void spatial_attn_kernel(
    const float* __restrict__ sinp, const float* __restrict__ cosp)
{
    extern __shared__ float smf[];
    float* ks = smf;
    float* vs = smf + NKEY * PDH;
    float* dots = smf + 2 * NKEY * PDH;

    const int bh = blockIdx.y;
    const int f  = blockIdx.x;
    const int tid = threadIdx.x;
    const size_t base = (size_t)bh * PN * PDH;

    for (int idx = tid; idx < NKEY * PDH; idx += 256) {
        int nrow = idx >> 6;
        int d = idx & 63;
        int gn = (nrow < PJ) ? nrow : (PJ + f * PNS + (nrow - PJ));
        float kv = g_k[base + (size_t)gn * PDH + d];
        float vv = g_v[base + (size_t)gn * PDH + d];
        if (nrow >= PJ && d < PROT) {
            int s = nrow - PJ;
            float c = cosp[s * PROT + d];
            float sn = sinp[s * PROT + d];
            float partner = g_k[base + (size_t)gn * PDH + (d ^ 1)];
            kv = (d & 1) ? (kv * c + partner * sn) : (kv * c - partner * sn);
        }
        ks[idx] = kv;
        vs[idx] = vv;
    }
    __syncthreads();

    if (tid < PNS) {
        const int s = tid;
        const int gn = PJ + f * PNS + s;
        float qr[PDH];
        const float* qp = g_q + base + (size_t)gn * PDH;
        #pragma unroll
        for (int d = 0; d < PDH; d++) qr[d] = qp[d];
        #pragma unroll
        for (int d = 0; d < PROT; d += 2) {
            float c0 = cosp[s * PROT + d],     s0 = sinp[s * PROT + d];
            float c1 = cosp[s * PROT + d + 1], s1 = sinp[s * PROT + d + 1];
            float a = qr[d], b2 = qr[d + 1];
            qr[d]     = a * c0 - b2 * s0;
            qr[d + 1] = b2 * c1 + a * s1;
        }

        float m = -1e30f, l = 0.f;
        float out[PDH];
        #pragma unroll
        for (int d = 0; d < PDH; d++) out[d] = 0.f;

        #pragma unroll
        for (int c = 0; c < 2; c++) {
            const int n0 = c * 110;
            float cmax = -1e30f;
            for (int nn = 0; nn < 110; nn++) {
                float dot = 0.f;
                #pragma unroll
                for (int d = 0; d < PDH; d++) dot += qr[d] * ks[(n0 + nn) * PDH + d];
                dots[tid * DPITCH + nn] = dot;
                cmax = fmaxf(cmax, dot);
            }
            float mnew = fmaxf(m, cmax);
            float resc = __expf(m - mnew);
            l *= resc;
            #pragma unroll
            for (int d = 0; d < PDH; d++) out[d] *= resc;
            m = mnew;
            for (int nn = 0; nn < 110; nn++) {
                float p = __expf(dots[tid * DPITCH + nn] - m);
                l += p;
                #pragma unroll
                for (int d = 0; d < PDH; d++) out[d] += p * vs[(n0 + nn) * PDH + d];
            }
        }

        const float inv = 1.f / l;
        const int b = bh >> 3, h = bh & 7;
        float* op = g_o + ((size_t)(b * PN + gn)) * (PH * PDH) + h * PDH;
        #pragma unroll
        for (int d = 0; d < PDH; d++) op[d] = out[d] * inv;
    }
}

// -------------------- launch --------------------------------------------------
extern "C" void kernel_launch(void* const* d_in, const int* in_sizes, int n_in,
                              void* d_out, int out_size)
{
    (void)in_sizes; (void)n_in; (void)out_size;
    const float* x      = (const float*)d_in[0];
    const float* w_qkv  = (const float*)d_in[1];
    const float* w_out  = (const float*)d_in[2];
    const float* b_out  = (const float*)d_in[3];
    const float* sinp   = (const float*)d_in[4];
    const float* cosp   = (const float*)d_in[5];
    float* out = (float*)d_out;

    cudaFuncSetAttribute(spatial_attn_kernel,
                         cudaFuncAttributeMaxDynamicSharedMemorySize, SPATIAL_SMEM);
    cudaFuncSetAttribute(mma_gemm_kernel<0>,
                         cudaFuncAttributeMaxDynamicSharedMemorySize, GEMM_SMEM);
    cudaFuncSetAttribute(mma_gemm_kernel<1>,
                         cudaFuncAttributeMaxDynamicSharedMemorySize, GEMM_SMEM);
    cudaFuncSetAttribute(joints_logits_kernel,
                         cudaFuncAttributeMaxDynamicSharedMemorySize, J1_SMEM);
    cudaFuncSetAttribute(joints_pv_kernel,
                         cudaFuncAttributeMaxDynamicSharedMemorySize, J2_SMEM);

    __nv_bfloat16 *xhi, *xlo, *ohi, *olo, *wqh, *wql, *woh, *wol;
    cudaGetSymbolAddress((void**)&xhi, g_xhi);
    cudaGetSymbolAddress((void**)&xlo, g_xlo);
    cudaGetSymbolAddress((void**)&ohi, g_ohi);
    cudaGetSymbolAddress((void**)&olo, g_olo);
    cudaGetSymbolAddress((void**)&wqh, g_wqkvT_hi);
    cudaGetSymbolAddress((void**)&wql, g_wqkvT_lo);
    cudaGetSymbolAddress((void**)&woh, g_woutT_hi);
    cudaGetSymbolAddress((void**)&wol, g_woutT_lo);

    // 1) split-convert x and transpose-convert weights
    {
        int n4 = PM1 * PDIM / 4;
        convert_split_kernel<<<(n4 + 255) / 256, 256>>>(x, xhi, xlo, n4);
        int nw = PDIM * NQKV;
        convert_wT_kernel<<<(nw + 255) / 256, 256>>>(w_qkv, wqh, wql, PDIM, NQKV);
        int nw2 = PDIM * PDIM;
        convert_wT_kernel<<<(nw2 + 255) / 256, 256>>>(w_out, woh, wol, PDIM, PDIM);
    }

    // 2) QKV projection (tensor cores via mma.sync, scatter to head-major)
    mma_gemm_kernel<0><<<dim3(NQKV / 128, (PM1 + 127) / 128), 256, GEMM_SMEM>>>(
        xhi, xlo, wqh, wql, nullptr, nullptr);

    // 3) joints attention (deterministic 3-kernel pipeline, V streamed once)
    joints_logits_kernel<<<dim3((PN + 255) / 256, PBH), 64, J1_SMEM>>>();
    joints_pv_kernel<<<dim3(4, PBH), 256, J2_SMEM>>>();
    joints_finish_kernel<<<PBH, 256>>>();

    // 4) spatial attention (single-dot-pass flash)
    spatial_attn_kernel<<<dim3(PF, PBH), 256, SPATIAL_SMEM>>>(sinp, cosp);

    // 5) output projection + bias
    {
        int n4 = PM1 * PDIM / 4;
        const float* gop;
        cudaGetSymbolAddress((void**)&gop, g_o);
        convert_split_kernel<<<(n4 + 255) / 256, 256>>>(gop, ohi, olo, n4);
    }
    mma_gemm_kernel<1><<<dim3(PDIM / 128, (PM1 + 127) / 128), 256, GEMM_SMEM>>>(
        ohi, olo, woh, wol, b_out, out);
}